// round 3
// baseline (speedup 1.0000x reference)
#include <cuda_runtime.h>
#include <cuda_bf16.h>
#include <math.h>

#define BB 2
#define NN 1024
#define TOK (BB*NN)
#define DIM 1024
#define DQK 128
#define NKEY 256
#define TOPK 32
#define DV 512
#define KCONV 5
#define OUT_MAIN (TOK*1024)

__device__ float g_invrms[TOK];
__device__ float g_x2[TOK*DIM];
__device__ float g_qpart[8*TOK*DQK];
__device__ float g_q[TOK*DQK];
__device__ float g_kp[1024*DQK];
__device__ float g_sc[TOK*1024];
__device__ float g_u[4];
__device__ float g_t[4];
__device__ float g_fs[2*TOK*TOPK];
__device__ int   g_fidx[2*TOK*TOPK];

__device__ __forceinline__ float fsign(float a, float b){ return (b >= 0.f) ? fabsf(a) : -fabsf(a); }
__device__ __forceinline__ unsigned sortable_f(float f){
    unsigned u = __float_as_uint(f);
    return (u & 0x80000000u) ? ~u : (u | 0x80000000u);
}
__device__ __forceinline__ float unsortable_f(unsigned s){
    unsigned u = (s & 0x80000000u) ? (s ^ 0x80000000u) : ~s;
    return __uint_as_float(u);
}

// LAPACK slasv2 port: SVD of 2x2 upper bidiagonal [[f,g],[0,h]]
__device__ void slasv2_dev(float f, float g, float h,
                           float& ssmin, float& ssmax,
                           float& snr, float& csr, float& snl, float& csl)
{
    float ft=f, fa=fabsf(f), ht=h, ha=fabsf(h);
    int pmax = 1;
    bool swp = (ha > fa);
    if (swp){ pmax = 3; float t; t=ft; ft=ht; ht=t; t=fa; fa=ha; ha=t; }
    float gt=g, ga=fabsf(g);
    float clt=0.f, crt=0.f, slt=0.f, srt=0.f;
    if (ga == 0.f){
        ssmin = ha; ssmax = fa; clt=1.f; crt=1.f; slt=0.f; srt=0.f;
    } else {
        bool gasmal = true;
        if (ga > fa){
            pmax = 2;
            if ((fa/ga) < 5.9604645e-08f){
                gasmal = false;
                ssmax = ga;
                ssmin = (ha > 1.f) ? (fa/(ga/ha)) : ((fa/ga)*ha);
                clt = 1.f; slt = ht/gt; srt = 1.f; crt = ft/gt;
            }
        }
        if (gasmal){
            float d_ = fa - ha;
            float l  = (d_ == fa) ? 1.f : d_/fa;
            float m  = gt/ft;
            float t  = 2.f - l;
            float mm = m*m, tt = t*t;
            float s  = sqrtf(tt + mm);
            float r_ = (l == 0.f) ? fabsf(m) : sqrtf(l*l + mm);
            float a_ = 0.5f*(s + r_);
            ssmin = ha/a_;
            ssmax = fa*a_;
            if (mm == 0.f){
                t = (l == 0.f) ? (fsign(2.f, ft)*fsign(1.f, gt))
                               : (gt/fsign(d_, ft) + m/t);
            } else {
                t = (m/(s + t) + m/(r_ + l))*(1.f + a_);
            }
            float l2 = sqrtf(t*t + 4.f);
            crt = 2.f/l2;
            srt = t/l2;
            clt = (crt + srt*m)/a_;
            slt = (ht/ft)*srt/a_;
        }
    }
    if (swp){ csl = srt; snl = crt; csr = slt; snr = clt; }
    else    { csl = clt; snl = slt; csr = crt; snr = srt; }
    float ts = 0.f;
    if (pmax == 1) ts = fsign(1.f, csr)*fsign(1.f, csl)*fsign(1.f, f);
    if (pmax == 2) ts = fsign(1.f, snr)*fsign(1.f, csl)*fsign(1.f, g);
    if (pmax == 3) ts = fsign(1.f, snr)*fsign(1.f, snl)*fsign(1.f, h);
    ssmax = fsign(ssmax, ts);
    ssmin = fsign(ssmin, ts*fsign(1.f, f)*fsign(1.f, h));
}

__global__ void svd_kernel(const float* __restrict__ core, float* __restrict__ d_out, int out_size)
{
    if (threadIdx.x != 0) return;
    float aux = 0.f;
    for (int hh = 0; hh < 2; hh++){
        float a = core[hh*4+0], b = core[hh*4+1];
        float c = core[hh*4+2], d = core[hh*4+3];
        // gebrd: Householder zeroing c
        float q00=1.f,q01=0.f,q10=0.f,q11=1.f;
        float d1, e1, d2;
        if (c != 0.f){
            float nrm  = sqrtf(a*a + c*c);
            float beta = (a >= 0.f) ? -nrm : nrm;
            float tau  = (beta - a)/beta;
            float v    = c/(a - beta);
            float w    = b + v*d;
            e1 = b - tau*w;
            d2 = d - tau*v*w;
            d1 = beta;
            q00 = 1.f - tau; q01 = -tau*v; q10 = -tau*v; q11 = 1.f - tau*v*v;
        } else { d1 = a; e1 = b; d2 = d; }
        float ssmin, ssmax, snr, csr, snl, csl;
        slasv2_dev(d1, e1, d2, ssmin, ssmax, snr, csr, snl, csl);
        float vt0 = csr, vt1 = snr;
        float s1 = ssmax;
        if (s1 < 0.f){ s1 = -s1; vt0 = -vt0; vt1 = -vt1; }
        float s2 = fabsf(ssmin);
        g_u[hh*2+0] = q00*csl + q01*snl;
        g_u[hh*2+1] = q10*csl + q11*snl;
        g_t[hh*2+0] = vt0;
        g_t[hh*2+1] = vt1;
        float r = s2 - 0.15f;
        if (r > 0.f) aux += r*r;
    }
    aux *= 0.1f;
    if (out_size > OUT_MAIN) d_out[OUT_MAIN] = aux;
}

__global__ void rms_kernel(const float* __restrict__ tokens)
{
    int tok = blockIdx.x;
    const float4* p = (const float4*)(tokens + (size_t)tok*DIM);
    float4 v = p[threadIdx.x];
    float s = v.x*v.x + v.y*v.y + v.z*v.z + v.w*v.w;
    for (int o = 16; o; o >>= 1) s += __shfl_xor_sync(0xFFFFFFFFu, s, o);
    __shared__ float ws[8];
    if ((threadIdx.x & 31) == 0) ws[threadIdx.x >> 5] = s;
    __syncthreads();
    if (threadIdx.x == 0){
        float t = 0.f;
        #pragma unroll
        for (int i = 0; i < 8; i++) t += ws[i];
        g_invrms[tok] = rsqrtf(t*(1.f/1024.f) + 1.1920929e-07f);
    }
}

__global__ void conv_kernel(const float* __restrict__ tokens,
                            const float* __restrict__ rms_w,
                            const float* __restrict__ conv_w,
                            const float* __restrict__ conv_b)
{
    int gid = blockIdx.x*256 + threadIdx.x;
    int d   = gid & (DIM-1);
    int tok = gid >> 10;
    int n   = tok & (NN-1);
    int bb  = tok >> 10;
    float acc = conv_b[d];
    float rw  = rms_w[d];
    #pragma unroll
    for (int k = 0; k < KCONV; k++){
        int nn = n - (KCONV-1) + k;
        if (nn >= 0){
            int t2 = (bb << 10) + nn;
            acc += tokens[(size_t)t2*DIM + d] * g_invrms[t2] * rw * conv_w[d*KCONV + k];
        }
    }
    g_x2[gid] = acc;
}

// C = A(M x K, row) * B(N x K, row)^T, 128x128 tiles, optional split-K
__global__ __launch_bounds__(256) void gemm128(
    const float* __restrict__ A, int lda,
    const float* __restrict__ B, int ldb,
    float* __restrict__ C, int ldc,
    int kLen, int zCStride)
{
    __shared__ float As[16][132];
    __shared__ float Bs[16][132];
    int tid = threadIdx.x;
    int tx = tid & 15, ty = tid >> 4;
    int m0 = blockIdx.y*128, n0 = blockIdx.x*128;
    int k0 = blockIdx.z*kLen;
    C += (size_t)blockIdx.z * zCStride;
    float acc[8][8];
    #pragma unroll
    for (int i = 0; i < 8; i++)
        #pragma unroll
        for (int j = 0; j < 8; j++) acc[i][j] = 0.f;
    const float* Ab = A + (size_t)m0*lda + k0;
    const float* Bb = B + (size_t)n0*ldb + k0;
    for (int kk = 0; kk < kLen; kk += 16){
        #pragma unroll
        for (int e = 0; e < 8; e++){
            int f = tid + e*256;
            int k = f & 15, m = f >> 4;
            As[k][m] = Ab[(size_t)m*lda + kk + k];
            Bs[k][m] = Bb[(size_t)m*ldb + kk + k];
        }
        __syncthreads();
        #pragma unroll
        for (int k = 0; k < 16; k++){
            float4 a0 = *(const float4*)&As[k][ty*8];
            float4 a1 = *(const float4*)&As[k][ty*8+4];
            float4 b0 = *(const float4*)&Bs[k][tx*8];
            float4 b1 = *(const float4*)&Bs[k][tx*8+4];
            float a[8] = {a0.x,a0.y,a0.z,a0.w,a1.x,a1.y,a1.z,a1.w};
            float b[8] = {b0.x,b0.y,b0.z,b0.w,b1.x,b1.y,b1.z,b1.w};
            #pragma unroll
            for (int i = 0; i < 8; i++)
                #pragma unroll
                for (int j = 0; j < 8; j++)
                    acc[i][j] += a[i]*b[j];
        }
        __syncthreads();
    }
    #pragma unroll
    for (int i = 0; i < 8; i++){
        float* Cr = C + (size_t)(m0 + ty*8 + i)*ldc + n0 + tx*8;
        #pragma unroll
        for (int j = 0; j < 8; j++) Cr[j] = acc[i][j];
    }
}

__global__ void ln_kernel(const float* __restrict__ qln_w)
{
    int tok = blockIdx.x, t = threadIdx.x;
    float v = 0.f;
    #pragma unroll
    for (int z = 0; z < 8; z++) v += g_qpart[(size_t)z*TOK*DQK + tok*DQK + t];
    float s = v;
    for (int o = 16; o; o >>= 1) s += __shfl_xor_sync(0xFFFFFFFFu, s, o);
    __shared__ float ws[4], ws2[4];
    int w = t >> 5, l = t & 31;
    if (l == 0) ws[w] = s;
    __syncthreads();
    float mu = (ws[0]+ws[1]+ws[2]+ws[3]) * (1.f/128.f);
    float dv = v - mu;
    float s2 = dv*dv;
    for (int o = 16; o; o >>= 1) s2 += __shfl_xor_sync(0xFFFFFFFFu, s2, o);
    if (l == 0) ws2[w] = s2;
    __syncthreads();
    float var = (ws2[0]+ws2[1]+ws2[2]+ws2[3]) * (1.f/128.f);
    g_q[tok*DQK + t] = dv * rsqrtf(var + 1e-5f) * qln_w[t];
}

__global__ void keysperm_kernel(const float* __restrict__ keys)
{
    int gid = blockIdx.x*256 + threadIdx.x;
    int d = gid & 127, j = gid >> 7;
    int c = j >> 9, rem = j & 511, m = rem >> 1, r = rem & 1;
    g_kp[gid] = keys[(((c*2 + r)*NKEY + m)*DQK) + d];
}

__device__ void bitonic_sort(unsigned long long* keys, int n, int tid, int nThreads)
{
    for (int k = 2; k <= n; k <<= 1){
        for (int j = k >> 1; j > 0; j >>= 1){
            for (int i = tid; i < n; i += nThreads){
                int ixj = i ^ j;
                if (ixj > i){
                    bool up = ((i & k) == 0);
                    unsigned long long x = keys[i], y = keys[ixj];
                    if ((x > y) == up){ keys[i] = y; keys[ixj] = x; }
                }
            }
            __syncthreads();
        }
    }
}

__global__ __launch_bounds__(256) void select_kernel(const float* __restrict__ core)
{
    __shared__ float rs[1024];
    __shared__ unsigned long long keys[1024];
    __shared__ int toprow[TOPK], topcol[TOPK];
    __shared__ float gg0[TOPK], gg1[TOPK], fc0[TOPK], fc1[TOPK];
    int tok = blockIdx.x, tid = threadIdx.x;
    #pragma unroll
    for (int e = 0; e < 4; e++) rs[tid + e*256] = g_sc[(size_t)tok*1024 + tid + e*256];
    __syncthreads();
    for (int h = 0; h < 2; h++){
        float u0 = g_u[h*2], u1 = g_u[h*2+1];
        float t0 = g_t[h*2], t1 = g_t[h*2+1];
        float c00 = core[h*4+0], c01 = core[h*4+1], c10 = core[h*4+2], c11 = core[h*4+3];
        // rows: top-32 of m_row
        {
            float val = rs[tid*2]*u0 + rs[tid*2+1]*u1;
            keys[tid] = (((unsigned long long)(~sortable_f(val))) << 32) | (unsigned)tid;
        }
        __syncthreads();
        bitonic_sort(keys, 256, tid, 256);
        if (tid < TOPK) toprow[tid] = (int)(keys[tid] & 0xFFFFFFFFu);
        __syncthreads();
        // cols: top-32 of m_col
        {
            float val = rs[512 + tid*2]*t0 + rs[512 + tid*2+1]*t1;
            keys[tid] = (((unsigned long long)(~sortable_f(val))) << 32) | (unsigned)tid;
        }
        __syncthreads();
        bitonic_sort(keys, 256, tid, 256);
        if (tid < TOPK) topcol[tid] = (int)(keys[tid] & 0xFFFFFFFFu);
        __syncthreads();
        if (tid < TOPK){
            float f0 = rs[2*toprow[tid]], f1 = rs[2*toprow[tid]+1];
            gg0[tid] = f0*c00 + f1*c10;
            gg1[tid] = f0*c01 + f1*c11;
            fc0[tid] = rs[512 + 2*topcol[tid]];
            fc1[tid] = rs[512 + 2*topcol[tid]+1];
        }
        __syncthreads();
        #pragma unroll
        for (int e = 0; e < 4; e++){
            int p = tid + e*256;
            int i = p >> 5, j = p & 31;
            float val = gg0[i]*fc0[j] + gg1[i]*fc1[j];
            keys[p] = (((unsigned long long)(~sortable_f(val))) << 32) | (unsigned)p;
        }
        __syncthreads();
        bitonic_sort(keys, 1024, tid, 256);
        if (tid < TOPK){
            unsigned long long kk = keys[tid];
            int p = (int)(kk & 0xFFFFFFFFu);
            int i = p >> 5, j = p & 31;
            float val = unsortable_f(~(unsigned)(kk >> 32));
            g_fs[((size_t)h*TOK + tok)*TOPK + tid] = 1.f/(1.f + expf(-val));
            g_fidx[((size_t)h*TOK + tok)*TOPK + tid] = toprow[i]*NKEY + topcol[j];
        }
        __syncthreads();
    }
}

__global__ void gather_kernel(const float* __restrict__ mem, float* __restrict__ out)
{
    int tok = blockIdx.x, h = blockIdx.y, tid = threadIdx.x;
    __shared__ float w[TOPK];
    __shared__ int   id[TOPK];
    if (tid < TOPK){
        w[tid]  = g_fs[((size_t)h*TOK + tok)*TOPK + tid];
        id[tid] = g_fidx[((size_t)h*TOK + tok)*TOPK + tid];
    }
    __syncthreads();
    float4 acc = {0.f,0.f,0.f,0.f};
    #pragma unroll 4
    for (int k = 0; k < TOPK; k++){
        const float4* row = (const float4*)(mem + (size_t)id[k]*DV);
        float4 v = row[tid];
        float ww = w[k];
        acc.x += ww*v.x; acc.y += ww*v.y; acc.z += ww*v.z; acc.w += ww*v.w;
    }
    ((float4*)(out + (size_t)tok*1024 + h*DV))[tid] = acc;
}

extern "C" void kernel_launch(void* const* d_in, const int* in_sizes, int n_in,
                              void* d_out, int out_size)
{
    const float* tokens  = (const float*)d_in[0];
    const float* rms_w   = (const float*)d_in[1];
    const float* conv_w  = (const float*)d_in[2];
    const float* conv_b  = (const float*)d_in[3];
    const float* wq      = (const float*)d_in[4];
    const float* qln_w   = (const float*)d_in[5];
    const float* keys    = (const float*)d_in[6];
    const float* core    = (const float*)d_in[7];
    const float* mems    = (const float*)d_in[8];
    float* out = (float*)d_out;

    float* qpart; cudaGetSymbolAddress((void**)&qpart, g_qpart);
    float* x2;    cudaGetSymbolAddress((void**)&x2, g_x2);
    float* q;     cudaGetSymbolAddress((void**)&q, g_q);
    float* kp;    cudaGetSymbolAddress((void**)&kp, g_kp);
    float* sc;    cudaGetSymbolAddress((void**)&sc, g_sc);

    svd_kernel<<<1, 32>>>(core, out, out_size);
    rms_kernel<<<TOK, 256>>>(tokens);
    conv_kernel<<<(TOK*DIM)/256, 256>>>(tokens, rms_w, conv_w, conv_b);
    // GEMM1: qpart[z] = x2 @ wq^T (split-K 8)
    gemm128<<<dim3(1,16,8), 256>>>(x2, DIM, wq, DIM, qpart, DQK, 128, TOK*DQK);
    ln_kernel<<<TOK, 128>>>(qln_w);
    keysperm_kernel<<<(1024*DQK)/256, 256>>>(keys);
    // GEMM2: sc = q @ kp^T
    gemm128<<<dim3(8,16,1), 256>>>(q, DQK, kp, DQK, sc, 1024, DQK, 0);
    select_kernel<<<TOK, 256>>>(core);
    gather_kernel<<<dim3(TOK,2), 128>>>(mems, out);
}

// round 4
// speedup vs baseline: 2.2399x; 2.2399x over previous
#include <cuda_runtime.h>
#include <cuda_bf16.h>
#include <math.h>

#define BB 2
#define NN 1024
#define TOK (BB*NN)
#define DIM 1024
#define DQK 128
#define NKEY 256
#define TOPK 32
#define DV 512
#define KCONV 5
#define OUT_MAIN (TOK*1024)

__device__ float g_invrms[TOK];
__device__ float g_x2[TOK*DIM];
__device__ float g_qpart[8*TOK*DQK];
__device__ float g_q[TOK*DQK];
__device__ float g_kp[1024*DQK];
__device__ float g_sc[TOK*1024];
__device__ float g_u[4];
__device__ float g_t[4];
__device__ float g_fs[2*TOK*TOPK];
__device__ int   g_fidx[2*TOK*TOPK];

__device__ __forceinline__ float fsign(float a, float b){ return (b >= 0.f) ? fabsf(a) : -fabsf(a); }
__device__ __forceinline__ unsigned sortable_f(float f){
    unsigned u = __float_as_uint(f);
    return (u & 0x80000000u) ? ~u : (u | 0x80000000u);
}
__device__ __forceinline__ float unsortable_f(unsigned s){
    unsigned u = (s & 0x80000000u) ? (s ^ 0x80000000u) : ~s;
    return __uint_as_float(u);
}
__device__ __forceinline__ unsigned long long pack_key(float v, unsigned idx){
    return (((unsigned long long)sortable_f(v)) << 32) | (unsigned long long)(0xFFFFFFFFu - idx);
}

// ---------- warp-level bitonic: sort 32 u64 keys descending across lanes ----------
__device__ __forceinline__ unsigned long long warp_sort_desc(unsigned long long v){
    int lane = threadIdx.x & 31;
    #pragma unroll
    for (int k = 2; k <= 32; k <<= 1){
        #pragma unroll
        for (int j = k >> 1; j > 0; j >>= 1){
            unsigned long long o = __shfl_xor_sync(0xFFFFFFFFu, v, j);
            bool sel = ((lane & j) == 0) == ((lane & k) == 0);
            unsigned long long mx = v > o ? v : o;
            unsigned long long mn = v > o ? o : v;
            v = sel ? mx : mn;
        }
    }
    return v;
}
// merge two descending 32-lists -> descending top-32 of the union
__device__ __forceinline__ unsigned long long warp_merge_desc(unsigned long long a, unsigned long long b){
    int lane = threadIdx.x & 31;
    unsigned long long br = __shfl_sync(0xFFFFFFFFu, b, 31 - lane);
    unsigned long long v = a > br ? a : br;
    #pragma unroll
    for (int j = 16; j > 0; j >>= 1){
        unsigned long long o = __shfl_xor_sync(0xFFFFFFFFu, v, j);
        unsigned long long mx = v > o ? v : o;
        unsigned long long mn = v > o ? o : v;
        v = ((lane & j) == 0) ? mx : mn;
    }
    return v;
}

// ---------------- SVD (LAPACK slasv2/gebrd port) + aux ----------------
__device__ void slasv2_dev(float f, float g, float h,
                           float& ssmin, float& ssmax,
                           float& snr, float& csr, float& snl, float& csl)
{
    float ft=f, fa=fabsf(f), ht=h, ha=fabsf(h);
    int pmax = 1;
    bool swp = (ha > fa);
    if (swp){ pmax = 3; float t; t=ft; ft=ht; ht=t; t=fa; fa=ha; ha=t; }
    float gt=g, ga=fabsf(g);
    float clt=0.f, crt=0.f, slt=0.f, srt=0.f;
    if (ga == 0.f){
        ssmin = ha; ssmax = fa; clt=1.f; crt=1.f; slt=0.f; srt=0.f;
    } else {
        bool gasmal = true;
        if (ga > fa){
            pmax = 2;
            if ((fa/ga) < 5.9604645e-08f){
                gasmal = false;
                ssmax = ga;
                ssmin = (ha > 1.f) ? (fa/(ga/ha)) : ((fa/ga)*ha);
                clt = 1.f; slt = ht/gt; srt = 1.f; crt = ft/gt;
            }
        }
        if (gasmal){
            float d_ = fa - ha;
            float l  = (d_ == fa) ? 1.f : d_/fa;
            float m  = gt/ft;
            float t  = 2.f - l;
            float mm = m*m, tt = t*t;
            float s  = sqrtf(tt + mm);
            float r_ = (l == 0.f) ? fabsf(m) : sqrtf(l*l + mm);
            float a_ = 0.5f*(s + r_);
            ssmin = ha/a_;
            ssmax = fa*a_;
            if (mm == 0.f){
                t = (l == 0.f) ? (fsign(2.f, ft)*fsign(1.f, gt))
                               : (gt/fsign(d_, ft) + m/t);
            } else {
                t = (m/(s + t) + m/(r_ + l))*(1.f + a_);
            }
            float l2 = sqrtf(t*t + 4.f);
            crt = 2.f/l2;
            srt = t/l2;
            clt = (crt + srt*m)/a_;
            slt = (ht/ft)*srt/a_;
        }
    }
    if (swp){ csl = srt; snl = crt; csr = slt; snr = clt; }
    else    { csl = clt; snl = slt; csr = crt; snr = srt; }
    float ts = 0.f;
    if (pmax == 1) ts = fsign(1.f, csr)*fsign(1.f, csl)*fsign(1.f, f);
    if (pmax == 2) ts = fsign(1.f, snr)*fsign(1.f, csl)*fsign(1.f, g);
    if (pmax == 3) ts = fsign(1.f, snr)*fsign(1.f, snl)*fsign(1.f, h);
    ssmax = fsign(ssmax, ts);
    ssmin = fsign(ssmin, ts*fsign(1.f, f)*fsign(1.f, h));
}

__global__ void svd_kernel(const float* __restrict__ core, float* __restrict__ d_out, int out_size)
{
    if (threadIdx.x != 0) return;
    float aux = 0.f;
    for (int hh = 0; hh < 2; hh++){
        float a = core[hh*4+0], b = core[hh*4+1];
        float c = core[hh*4+2], d = core[hh*4+3];
        float q00=1.f,q01=0.f,q10=0.f,q11=1.f;
        float d1, e1, d2;
        if (c != 0.f){
            float nrm  = sqrtf(a*a + c*c);
            float beta = (a >= 0.f) ? -nrm : nrm;
            float tau  = (beta - a)/beta;
            float v    = c/(a - beta);
            float w    = b + v*d;
            e1 = b - tau*w;
            d2 = d - tau*v*w;
            d1 = beta;
            q00 = 1.f - tau; q01 = -tau*v; q10 = -tau*v; q11 = 1.f - tau*v*v;
        } else { d1 = a; e1 = b; d2 = d; }
        float ssmin, ssmax, snr, csr, snl, csl;
        slasv2_dev(d1, e1, d2, ssmin, ssmax, snr, csr, snl, csl);
        float vt0 = csr, vt1 = snr;
        float s1 = ssmax;
        if (s1 < 0.f){ s1 = -s1; vt0 = -vt0; vt1 = -vt1; }
        float s2 = fabsf(ssmin);
        g_u[hh*2+0] = q00*csl + q01*snl;
        g_u[hh*2+1] = q10*csl + q11*snl;
        g_t[hh*2+0] = vt0;
        g_t[hh*2+1] = vt1;
        float r = s2 - 0.15f;
        if (r > 0.f) aux += r*r;
    }
    aux *= 0.1f;
    if (out_size > OUT_MAIN) d_out[OUT_MAIN] = aux;
}

__global__ void rms_kernel(const float* __restrict__ tokens)
{
    int tok = blockIdx.x;
    const float4* p = (const float4*)(tokens + (size_t)tok*DIM);
    float4 v = p[threadIdx.x];
    float s = v.x*v.x + v.y*v.y + v.z*v.z + v.w*v.w;
    for (int o = 16; o; o >>= 1) s += __shfl_xor_sync(0xFFFFFFFFu, s, o);
    __shared__ float ws[8];
    if ((threadIdx.x & 31) == 0) ws[threadIdx.x >> 5] = s;
    __syncthreads();
    if (threadIdx.x == 0){
        float t = 0.f;
        #pragma unroll
        for (int i = 0; i < 8; i++) t += ws[i];
        g_invrms[tok] = rsqrtf(t*(1.f/1024.f) + 1.1920929e-07f);
    }
}

__global__ void conv_kernel(const float* __restrict__ tokens,
                            const float* __restrict__ rms_w,
                            const float* __restrict__ conv_w,
                            const float* __restrict__ conv_b)
{
    int gid = blockIdx.x*256 + threadIdx.x;
    int d   = gid & (DIM-1);
    int tok = gid >> 10;
    int n   = tok & (NN-1);
    int bb  = tok >> 10;
    float acc = conv_b[d];
    float rw  = rms_w[d];
    #pragma unroll
    for (int k = 0; k < KCONV; k++){
        int nn = n - (KCONV-1) + k;
        if (nn >= 0){
            int t2 = (bb << 10) + nn;
            acc += tokens[(size_t)t2*DIM + d] * g_invrms[t2] * rw * conv_w[d*KCONV + k];
        }
    }
    g_x2[gid] = acc;
}

// C = A(MxK,row) * B(NxK,row)^T.  Tile 128x64, 256 threads, 8x4 per thread.
__global__ __launch_bounds__(256) void gemm128x64(
    const float* __restrict__ A, int lda,
    const float* __restrict__ B, int ldb,
    float* __restrict__ C, int ldc,
    int kLen, int zCStride)
{
    __shared__ float As[16][132];
    __shared__ float Bs[16][68];
    int tid = threadIdx.x;
    int tx = tid & 15, ty = tid >> 4;
    int m0 = blockIdx.y*128, n0 = blockIdx.x*64;
    int k0 = blockIdx.z*kLen;
    C += (size_t)blockIdx.z * zCStride;
    float acc[8][4];
    #pragma unroll
    for (int i = 0; i < 8; i++)
        #pragma unroll
        for (int j = 0; j < 4; j++) acc[i][j] = 0.f;
    const float* Ab = A + (size_t)m0*lda + k0;
    const float* Bb = B + (size_t)n0*ldb + k0;
    for (int kk = 0; kk < kLen; kk += 16){
        #pragma unroll
        for (int e = 0; e < 8; e++){
            int f = tid + e*256;
            As[f & 15][f >> 4] = Ab[(size_t)(f >> 4)*lda + kk + (f & 15)];
        }
        #pragma unroll
        for (int e = 0; e < 4; e++){
            int f = tid + e*256;
            Bs[f & 15][f >> 4] = Bb[(size_t)(f >> 4)*ldb + kk + (f & 15)];
        }
        __syncthreads();
        #pragma unroll
        for (int k = 0; k < 16; k++){
            float4 a0 = *(const float4*)&As[k][ty*8];
            float4 a1 = *(const float4*)&As[k][ty*8+4];
            float4 b0 = *(const float4*)&Bs[k][tx*4];
            float a[8] = {a0.x,a0.y,a0.z,a0.w,a1.x,a1.y,a1.z,a1.w};
            float b[4] = {b0.x,b0.y,b0.z,b0.w};
            #pragma unroll
            for (int i = 0; i < 8; i++)
                #pragma unroll
                for (int j = 0; j < 4; j++)
                    acc[i][j] += a[i]*b[j];
        }
        __syncthreads();
    }
    #pragma unroll
    for (int i = 0; i < 8; i++){
        float* Cr = C + (size_t)(m0 + ty*8 + i)*ldc + n0 + tx*4;
        float4 v = {acc[i][0], acc[i][1], acc[i][2], acc[i][3]};
        *(float4*)Cr = v;
    }
}

__global__ void ln_kernel(const float* __restrict__ qln_w)
{
    int tok = blockIdx.x, t = threadIdx.x;
    float v = 0.f;
    #pragma unroll
    for (int z = 0; z < 8; z++) v += g_qpart[(size_t)z*TOK*DQK + tok*DQK + t];
    float s = v;
    for (int o = 16; o; o >>= 1) s += __shfl_xor_sync(0xFFFFFFFFu, s, o);
    __shared__ float ws[4], ws2[4];
    int w = t >> 5, l = t & 31;
    if (l == 0) ws[w] = s;
    __syncthreads();
    float mu = (ws[0]+ws[1]+ws[2]+ws[3]) * (1.f/128.f);
    float dv = v - mu;
    float s2 = dv*dv;
    for (int o = 16; o; o >>= 1) s2 += __shfl_xor_sync(0xFFFFFFFFu, s2, o);
    if (l == 0) ws2[w] = s2;
    __syncthreads();
    float var = (ws2[0]+ws2[1]+ws2[2]+ws2[3]) * (1.f/128.f);
    g_q[tok*DQK + t] = dv * rsqrtf(var + 1e-5f) * qln_w[t];
}

__global__ void keysperm_kernel(const float* __restrict__ keys)
{
    int gid = blockIdx.x*256 + threadIdx.x;
    int d = gid & 127, j = gid >> 7;
    int c = j >> 9, rem = j & 511, m = rem >> 1, r = rem & 1;
    g_kp[gid] = keys[(((c*2 + r)*NKEY + m)*DQK) + d];
}

// ---------------- fused two-level top-k via warp sorts ----------------
__global__ __launch_bounds__(256) void select_kernel(const float* __restrict__ core)
{
    __shared__ float rs[1024];
    __shared__ unsigned long long bufA[16][32];
    __shared__ unsigned long long bufB[8][32];
    __shared__ int ridx[32], cidx[32];
    __shared__ float gg0[32], gg1[32], fc0[32], fc1[32];
    int tok = blockIdx.x, tid = threadIdx.x;
    int lane = tid & 31, w = tid >> 5;
    #pragma unroll
    for (int e = 0; e < 4; e++) rs[tid + e*256] = g_sc[(size_t)tok*1024 + tid + e*256];
    __syncthreads();
    for (int h = 0; h < 2; h++){
        float u0 = g_u[h*2], u1 = g_u[h*2+1];
        float t0 = g_t[h*2], t1 = g_t[h*2+1];
        float c00 = core[h*4+0], c01 = core[h*4+1], c10 = core[h*4+2], c11 = core[h*4+3];
        // stage A: per-warp chunk sorts (rows + cols)
        {
            int m = w*32 + lane;
            float rv = rs[2*m]*u0 + rs[2*m+1]*u1;
            float cv = rs[512 + 2*m]*t0 + rs[512 + 2*m+1]*t1;
            bufA[w][lane]     = warp_sort_desc(pack_key(rv, (unsigned)m));
            bufA[8 + w][lane] = warp_sort_desc(pack_key(cv, (unsigned)m));
        }
        __syncthreads();
        // merge round 1: 8 lists -> 4 per side
        {
            if (w < 4)
                bufB[w][lane] = warp_merge_desc(bufA[2*w][lane], bufA[2*w+1][lane]);
            else {
                int p = w - 4;
                bufB[4 + p][lane] = warp_merge_desc(bufA[8 + 2*p][lane], bufA[8 + 2*p + 1][lane]);
            }
        }
        __syncthreads();
        // merge round 2: 4 -> 2 per side
        if (w < 2)
            bufA[w][lane] = warp_merge_desc(bufB[2*w][lane], bufB[2*w+1][lane]);
        else if (w >= 4 && w < 6){
            int p = w - 4;
            bufA[8 + p][lane] = warp_merge_desc(bufB[4 + 2*p][lane], bufB[4 + 2*p + 1][lane]);
        }
        __syncthreads();
        // merge round 3: final row/col top-32 + score-factor precompute
        if (w == 0){
            unsigned long long r = warp_merge_desc(bufA[0][lane], bufA[1][lane]);
            int mi = (int)(0xFFFFFFFFu - (unsigned)r);
            ridx[lane] = mi;
            float f0 = rs[2*mi], f1 = rs[2*mi+1];
            gg0[lane] = f0*c00 + f1*c10;
            gg1[lane] = f0*c01 + f1*c11;
        }
        if (w == 4){
            unsigned long long r = warp_merge_desc(bufA[8][lane], bufA[9][lane]);
            int mi = (int)(0xFFFFFFFFu - (unsigned)r);
            cidx[lane] = mi;
            fc0[lane] = rs[512 + 2*mi];
            fc1[lane] = rs[512 + 2*mi+1];
        }
        __syncthreads();
        // stage B: 32x32 scores, top-32 of 1024
        unsigned long long v[4];
        #pragma unroll
        for (int c = 0; c < 4; c++){
            int i = w*4 + c;
            float val = gg0[i]*fc0[lane] + gg1[i]*fc1[lane];
            v[c] = warp_sort_desc(pack_key(val, (unsigned)(i*32 + lane)));
        }
        unsigned long long m0 = warp_merge_desc(v[0], v[1]);
        unsigned long long m1 = warp_merge_desc(v[2], v[3]);
        bufA[w][lane] = warp_merge_desc(m0, m1);
        __syncthreads();
        if (w < 4) bufB[w][lane] = warp_merge_desc(bufA[2*w][lane], bufA[2*w+1][lane]);
        __syncthreads();
        if (w < 2) bufA[w][lane] = warp_merge_desc(bufB[2*w][lane], bufB[2*w+1][lane]);
        __syncthreads();
        if (w == 0){
            unsigned long long r = warp_merge_desc(bufA[0][lane], bufA[1][lane]);
            unsigned p = 0xFFFFFFFFu - (unsigned)r;
            float val = unsortable_f((unsigned)(r >> 32));
            g_fs[((size_t)h*TOK + tok)*TOPK + lane] = 1.f/(1.f + expf(-val));
            g_fidx[((size_t)h*TOK + tok)*TOPK + lane] = ridx[p >> 5]*NKEY + cidx[p & 31];
        }
        __syncthreads();
    }
}

__global__ __launch_bounds__(512) void gather_kernel(const float* __restrict__ mem,
                                                     float* __restrict__ out)
{
    int tok = blockIdx.x, tid = threadIdx.x;
    int h = tid >> 8, sub = (tid >> 7) & 1, t = tid & 127;
    __shared__ float w[2][TOPK];
    __shared__ int   id[2][TOPK];
    __shared__ float4 part[2][128];
    if (tid < 64){
        int hh = tid >> 5, k = tid & 31;
        w[hh][k]  = g_fs[((size_t)hh*TOK + tok)*TOPK + k];
        id[hh][k] = g_fidx[((size_t)hh*TOK + tok)*TOPK + k];
    }
    __syncthreads();
    float4 acc = {0.f,0.f,0.f,0.f};
    #pragma unroll
    for (int kk = 0; kk < 16; kk++){
        int k = sub*16 + kk;
        const float4* row = (const float4*)(mem + (size_t)id[h][k]*DV);
        float4 v = __ldg(row + t);
        float ww = w[h][k];
        acc.x += ww*v.x; acc.y += ww*v.y; acc.z += ww*v.z; acc.w += ww*v.w;
    }
    if (sub == 0) part[h][t] = acc;
    __syncthreads();
    if (sub == 1){
        float4 p = part[h][t];
        acc.x += p.x; acc.y += p.y; acc.z += p.z; acc.w += p.w;
        ((float4*)(out + (size_t)tok*1024 + h*DV))[t] = acc;
    }
}

extern "C" void kernel_launch(void* const* d_in, const int* in_sizes, int n_in,
                              void* d_out, int out_size)
{
    const float* tokens  = (const float*)d_in[0];
    const float* rms_w   = (const float*)d_in[1];
    const float* conv_w  = (const float*)d_in[2];
    const float* conv_b  = (const float*)d_in[3];
    const float* wq      = (const float*)d_in[4];
    const float* qln_w   = (const float*)d_in[5];
    const float* keys    = (const float*)d_in[6];
    const float* core    = (const float*)d_in[7];
    const float* mems    = (const float*)d_in[8];
    float* out = (float*)d_out;

    float* qpart; cudaGetSymbolAddress((void**)&qpart, g_qpart);
    float* x2;    cudaGetSymbolAddress((void**)&x2, g_x2);
    float* q;     cudaGetSymbolAddress((void**)&q, g_q);
    float* kp;    cudaGetSymbolAddress((void**)&kp, g_kp);
    float* sc;    cudaGetSymbolAddress((void**)&sc, g_sc);

    svd_kernel<<<1, 32>>>(core, out, out_size);
    rms_kernel<<<TOK, 256>>>(tokens);
    conv_kernel<<<(TOK*DIM)/256, 256>>>(tokens, rms_w, conv_w, conv_b);
    // GEMM1: qpart[z] = x2 @ wq^T (split-K 8), N=128 -> grid.x=2
    gemm128x64<<<dim3(2,16,8), 256>>>(x2, DIM, wq, DIM, qpart, DQK, 128, TOK*DQK);
    ln_kernel<<<TOK, 128>>>(qln_w);
    keysperm_kernel<<<(1024*DQK)/256, 256>>>(keys);
    // GEMM2: sc = q @ kp^T, N=1024 -> grid.x=16
    gemm128x64<<<dim3(16,16,1), 256>>>(q, DQK, kp, DQK, sc, 1024, DQK, 0);
    select_kernel<<<TOK, 256>>>(core);
    gather_kernel<<<TOK, 512>>>(mems, out);
}

// round 5
// speedup vs baseline: 2.3351x; 1.0425x over previous
#include <cuda_runtime.h>
#include <cuda_bf16.h>
#include <math.h>

#define BB 2
#define NN 1024
#define TOK (BB*NN)
#define DIM 1024
#define DQK 128
#define NKEY 256
#define TOPK 32
#define DV 512
#define KCONV 5
#define OUT_MAIN (TOK*1024)

__device__ float g_invrms[TOK];
__device__ float g_x2[TOK*DIM];
__device__ float g_qpart[8*TOK*DQK];
__device__ float g_q[TOK*DQK];
__device__ float g_sc[TOK*1024];
__device__ float g_fs[2*TOK*TOPK];
__device__ int   g_fidx[2*TOK*TOPK];

__device__ __forceinline__ float fsign(float a, float b){ return (b >= 0.f) ? fabsf(a) : -fabsf(a); }
__device__ __forceinline__ unsigned sortable_f(float f){
    unsigned u = __float_as_uint(f);
    return (u & 0x80000000u) ? ~u : (u | 0x80000000u);
}
__device__ __forceinline__ float unsortable_f(unsigned s){
    unsigned u = (s & 0x80000000u) ? (s ^ 0x80000000u) : ~s;
    return __uint_as_float(u);
}
__device__ __forceinline__ unsigned long long pack_key(float v, unsigned idx){
    return (((unsigned long long)sortable_f(v)) << 32) | (unsigned long long)(0xFFFFFFFFu - idx);
}

// ---------- warp-level bitonic sort/merge on u64 keys ----------
__device__ __forceinline__ unsigned long long warp_sort_desc(unsigned long long v){
    int lane = threadIdx.x & 31;
    #pragma unroll
    for (int k = 2; k <= 32; k <<= 1){
        #pragma unroll
        for (int j = k >> 1; j > 0; j >>= 1){
            unsigned long long o = __shfl_xor_sync(0xFFFFFFFFu, v, j);
            bool sel = ((lane & j) == 0) == ((lane & k) == 0);
            unsigned long long mx = v > o ? v : o;
            unsigned long long mn = v > o ? o : v;
            v = sel ? mx : mn;
        }
    }
    return v;
}
__device__ __forceinline__ unsigned long long warp_merge_desc(unsigned long long a, unsigned long long b){
    int lane = threadIdx.x & 31;
    unsigned long long br = __shfl_sync(0xFFFFFFFFu, b, 31 - lane);
    unsigned long long v = a > br ? a : br;
    #pragma unroll
    for (int j = 16; j > 0; j >>= 1){
        unsigned long long o = __shfl_xor_sync(0xFFFFFFFFu, v, j);
        unsigned long long mx = v > o ? v : o;
        unsigned long long mn = v > o ? o : v;
        v = ((lane & j) == 0) ? mx : mn;
    }
    return v;
}

// ---------------- LAPACK slasv2 port ----------------
__device__ void slasv2_dev(float f, float g, float h,
                           float& ssmin, float& ssmax,
                           float& snr, float& csr, float& snl, float& csl)
{
    float ft=f, fa=fabsf(f), ht=h, ha=fabsf(h);
    int pmax = 1;
    bool swp = (ha > fa);
    if (swp){ pmax = 3; float t; t=ft; ft=ht; ht=t; t=fa; fa=ha; ha=t; }
    float gt=g, ga=fabsf(g);
    float clt=0.f, crt=0.f, slt=0.f, srt=0.f;
    if (ga == 0.f){
        ssmin = ha; ssmax = fa; clt=1.f; crt=1.f; slt=0.f; srt=0.f;
    } else {
        bool gasmal = true;
        if (ga > fa){
            pmax = 2;
            if ((fa/ga) < 5.9604645e-08f){
                gasmal = false;
                ssmax = ga;
                ssmin = (ha > 1.f) ? (fa/(ga/ha)) : ((fa/ga)*ha);
                clt = 1.f; slt = ht/gt; srt = 1.f; crt = ft/gt;
            }
        }
        if (gasmal){
            float d_ = fa - ha;
            float l  = (d_ == fa) ? 1.f : d_/fa;
            float m  = gt/ft;
            float t  = 2.f - l;
            float mm = m*m, tt = t*t;
            float s  = sqrtf(tt + mm);
            float r_ = (l == 0.f) ? fabsf(m) : sqrtf(l*l + mm);
            float a_ = 0.5f*(s + r_);
            ssmin = ha/a_;
            ssmax = fa*a_;
            if (mm == 0.f){
                t = (l == 0.f) ? (fsign(2.f, ft)*fsign(1.f, gt))
                               : (gt/fsign(d_, ft) + m/t);
            } else {
                t = (m/(s + t) + m/(r_ + l))*(1.f + a_);
            }
            float l2 = sqrtf(t*t + 4.f);
            crt = 2.f/l2;
            srt = t/l2;
            clt = (crt + srt*m)/a_;
            slt = (ht/ft)*srt/a_;
        }
    }
    if (swp){ csl = srt; snl = crt; csr = slt; snr = clt; }
    else    { csl = clt; snl = slt; csr = crt; snr = srt; }
    float ts = 0.f;
    if (pmax == 1) ts = fsign(1.f, csr)*fsign(1.f, csl)*fsign(1.f, f);
    if (pmax == 2) ts = fsign(1.f, snr)*fsign(1.f, csl)*fsign(1.f, g);
    if (pmax == 3) ts = fsign(1.f, snr)*fsign(1.f, snl)*fsign(1.f, h);
    ssmax = fsign(ssmax, ts);
    ssmin = fsign(ssmin, ts*fsign(1.f, f)*fsign(1.f, h));
}

// per-head SVD: writes u0,u1,t0,t1 and partial aux
__device__ void svd2x2(const float* core, int hh, float& u0, float& u1,
                       float& t0, float& t1, float& auxp)
{
    float a = core[hh*4+0], b = core[hh*4+1];
    float c = core[hh*4+2], d = core[hh*4+3];
    float q00=1.f,q01=0.f,q10=0.f,q11=1.f;
    float d1, e1, d2;
    if (c != 0.f){
        float nrm  = sqrtf(a*a + c*c);
        float beta = (a >= 0.f) ? -nrm : nrm;
        float tau  = (beta - a)/beta;
        float v    = c/(a - beta);
        float w    = b + v*d;
        e1 = b - tau*w;
        d2 = d - tau*v*w;
        d1 = beta;
        q00 = 1.f - tau; q01 = -tau*v; q10 = -tau*v; q11 = 1.f - tau*v*v;
    } else { d1 = a; e1 = b; d2 = d; }
    float ssmin, ssmax, snr, csr, snl, csl;
    slasv2_dev(d1, e1, d2, ssmin, ssmax, snr, csr, snl, csl);
    float vt0 = csr, vt1 = snr;
    float s1 = ssmax;
    if (s1 < 0.f){ s1 = -s1; vt0 = -vt0; vt1 = -vt1; }
    float s2 = fabsf(ssmin);
    u0 = q00*csl + q01*snl;
    u1 = q10*csl + q11*snl;
    t0 = vt0;
    t1 = vt1;
    float r = s2 - 0.15f;
    auxp = (r > 0.f) ? r*r : 0.f;
}

__global__ void rms_kernel(const float* __restrict__ tokens)
{
    int tok = blockIdx.x;
    const float4* p = (const float4*)(tokens + (size_t)tok*DIM);
    float4 v = p[threadIdx.x];
    float s = v.x*v.x + v.y*v.y + v.z*v.z + v.w*v.w;
    for (int o = 16; o; o >>= 1) s += __shfl_xor_sync(0xFFFFFFFFu, s, o);
    __shared__ float ws[8];
    if ((threadIdx.x & 31) == 0) ws[threadIdx.x >> 5] = s;
    __syncthreads();
    if (threadIdx.x == 0){
        float t = 0.f;
        #pragma unroll
        for (int i = 0; i < 8; i++) t += ws[i];
        g_invrms[tok] = rsqrtf(t*(1.f/1024.f) + 1.1920929e-07f);
    }
}

// sliding-window conv: each thread computes 4 consecutive n for one d
__global__ void conv_kernel(const float* __restrict__ tokens,
                            const float* __restrict__ rms_w,
                            const float* __restrict__ conv_w,
                            const float* __restrict__ conv_b)
{
    int gid = blockIdx.x*256 + threadIdx.x;        // TOK/4 * DIM threads
    int d   = gid & (DIM-1);
    int grp = gid >> 10;                           // 0..TOK/4-1
    int ng  = grp & (NN/4 - 1);
    int bb  = grp >> 8;
    float rw = rms_w[d];
    float wv[KCONV];
    #pragma unroll
    for (int k = 0; k < KCONV; k++) wv[k] = conv_w[d*KCONV + k];
    float xv[8];
    #pragma unroll
    for (int j = 0; j < 8; j++){
        int nn = ng*4 - 4 + j;
        if (nn >= 0){
            int t2 = (bb << 10) + nn;
            xv[j] = tokens[(size_t)t2*DIM + d] * g_invrms[t2] * rw;
        } else xv[j] = 0.f;
    }
    float cb = conv_b[d];
    #pragma unroll
    for (int i = 0; i < 4; i++){
        float acc = cb;
        #pragma unroll
        for (int k = 0; k < KCONV; k++) acc += wv[k]*xv[i+k];
        g_x2[(size_t)((bb << 10) + ng*4 + i)*DIM + d] = acc;
    }
}

// ---------------- GEMM1: qpart[z] = x2 @ wq^T, split-K=8, double-buffered ----------------
__global__ __launch_bounds__(256) void gemm_q(const float* __restrict__ A,
                                              const float* __restrict__ B,
                                              float* __restrict__ C)
{
    __shared__ float As[2][16][132];
    __shared__ float Bs[2][16][68];
    int tid = threadIdx.x, tx = tid & 15, ty = tid >> 4;
    int m0 = blockIdx.y*128, n0 = blockIdx.x*64, k0 = blockIdx.z*128;
    C += (size_t)blockIdx.z*(TOK*DQK);
    const float* Ab = A + (size_t)m0*DIM + k0;
    const float* Bb = B + (size_t)n0*DIM + k0;
    float acc[8][4];
    #pragma unroll
    for (int i = 0; i < 8; i++)
        #pragma unroll
        for (int j = 0; j < 4; j++) acc[i][j] = 0.f;
    float ra[8], rb[4];
    #pragma unroll
    for (int e = 0; e < 8; e++){ int f = tid + e*256; ra[e] = Ab[(size_t)(f >> 4)*DIM + (f & 15)]; }
    #pragma unroll
    for (int e = 0; e < 4; e++){ int f = tid + e*256; rb[e] = Bb[(size_t)(f >> 4)*DIM + (f & 15)]; }
    #pragma unroll
    for (int e = 0; e < 8; e++){ int f = tid + e*256; As[0][f & 15][f >> 4] = ra[e]; }
    #pragma unroll
    for (int e = 0; e < 4; e++){ int f = tid + e*256; Bs[0][f & 15][f >> 4] = rb[e]; }
    __syncthreads();
    int cur = 0;
    for (int kk = 0; kk < 128; kk += 16){
        bool nxt = (kk + 16) < 128;
        if (nxt){
            #pragma unroll
            for (int e = 0; e < 8; e++){ int f = tid + e*256; ra[e] = Ab[(size_t)(f >> 4)*DIM + kk + 16 + (f & 15)]; }
            #pragma unroll
            for (int e = 0; e < 4; e++){ int f = tid + e*256; rb[e] = Bb[(size_t)(f >> 4)*DIM + kk + 16 + (f & 15)]; }
        }
        #pragma unroll
        for (int k = 0; k < 16; k++){
            float4 a0 = *(const float4*)&As[cur][k][ty*8];
            float4 a1 = *(const float4*)&As[cur][k][ty*8+4];
            float4 b0 = *(const float4*)&Bs[cur][k][tx*4];
            float a[8] = {a0.x,a0.y,a0.z,a0.w,a1.x,a1.y,a1.z,a1.w};
            float b[4] = {b0.x,b0.y,b0.z,b0.w};
            #pragma unroll
            for (int i = 0; i < 8; i++)
                #pragma unroll
                for (int j = 0; j < 4; j++)
                    acc[i][j] += a[i]*b[j];
        }
        if (nxt){
            #pragma unroll
            for (int e = 0; e < 8; e++){ int f = tid + e*256; As[cur^1][f & 15][f >> 4] = ra[e]; }
            #pragma unroll
            for (int e = 0; e < 4; e++){ int f = tid + e*256; Bs[cur^1][f & 15][f >> 4] = rb[e]; }
            __syncthreads();
            cur ^= 1;
        }
    }
    #pragma unroll
    for (int i = 0; i < 8; i++){
        float4 v = {acc[i][0], acc[i][1], acc[i][2], acc[i][3]};
        *(float4*)(C + (size_t)(m0 + ty*8 + i)*DQK + n0 + tx*4) = v;
    }
}

// ---------------- GEMM2: sc = q @ kp^T with fused keys permutation ----------------
__global__ __launch_bounds__(256) void gemm_sc(const float* __restrict__ A,
                                               const float* __restrict__ keys,
                                               float* __restrict__ C)
{
    __shared__ float As[2][16][132];
    __shared__ float Bs[2][16][68];
    int tid = threadIdx.x, tx = tid & 15, ty = tid >> 4;
    int m0 = blockIdx.y*128, n0 = blockIdx.x*64;
    const float* Ab = A + (size_t)m0*DQK;
    // precompute permuted base offsets for this thread's 4 B rows
    size_t brow[4];
    #pragma unroll
    for (int e = 0; e < 4; e++){
        int f = tid + e*256;
        int j = n0 + (f >> 4);
        int c = j >> 9, rem = j & 511, m = rem >> 1, r = rem & 1;
        brow[e] = (size_t)(((c*2 + r)*NKEY + m))*DQK;
    }
    float acc[8][4];
    #pragma unroll
    for (int i = 0; i < 8; i++)
        #pragma unroll
        for (int j = 0; j < 4; j++) acc[i][j] = 0.f;
    float ra[8], rb[4];
    #pragma unroll
    for (int e = 0; e < 8; e++){ int f = tid + e*256; ra[e] = Ab[(size_t)(f >> 4)*DQK + (f & 15)]; }
    #pragma unroll
    for (int e = 0; e < 4; e++){ int f = tid + e*256; rb[e] = keys[brow[e] + (f & 15)]; }
    #pragma unroll
    for (int e = 0; e < 8; e++){ int f = tid + e*256; As[0][f & 15][f >> 4] = ra[e]; }
    #pragma unroll
    for (int e = 0; e < 4; e++){ int f = tid + e*256; Bs[0][f & 15][f >> 4] = rb[e]; }
    __syncthreads();
    int cur = 0;
    for (int kk = 0; kk < 128; kk += 16){
        bool nxt = (kk + 16) < 128;
        if (nxt){
            #pragma unroll
            for (int e = 0; e < 8; e++){ int f = tid + e*256; ra[e] = Ab[(size_t)(f >> 4)*DQK + kk + 16 + (f & 15)]; }
            #pragma unroll
            for (int e = 0; e < 4; e++){ int f = tid + e*256; rb[e] = keys[brow[e] + kk + 16 + (f & 15)]; }
        }
        #pragma unroll
        for (int k = 0; k < 16; k++){
            float4 a0 = *(const float4*)&As[cur][k][ty*8];
            float4 a1 = *(const float4*)&As[cur][k][ty*8+4];
            float4 b0 = *(const float4*)&Bs[cur][k][tx*4];
            float a[8] = {a0.x,a0.y,a0.z,a0.w,a1.x,a1.y,a1.z,a1.w};
            float b[4] = {b0.x,b0.y,b0.z,b0.w};
            #pragma unroll
            for (int i = 0; i < 8; i++)
                #pragma unroll
                for (int j = 0; j < 4; j++)
                    acc[i][j] += a[i]*b[j];
        }
        if (nxt){
            #pragma unroll
            for (int e = 0; e < 8; e++){ int f = tid + e*256; As[cur^1][f & 15][f >> 4] = ra[e]; }
            #pragma unroll
            for (int e = 0; e < 4; e++){ int f = tid + e*256; Bs[cur^1][f & 15][f >> 4] = rb[e]; }
            __syncthreads();
            cur ^= 1;
        }
    }
    #pragma unroll
    for (int i = 0; i < 8; i++){
        float4 v = {acc[i][0], acc[i][1], acc[i][2], acc[i][3]};
        *(float4*)(C + (size_t)(m0 + ty*8 + i)*1024 + n0 + tx*4) = v;
    }
}

__global__ void ln_kernel(const float* __restrict__ qln_w)
{
    int tok = blockIdx.x, t = threadIdx.x;
    float v = 0.f;
    #pragma unroll
    for (int z = 0; z < 8; z++) v += g_qpart[(size_t)z*TOK*DQK + tok*DQK + t];
    float s = v;
    for (int o = 16; o; o >>= 1) s += __shfl_xor_sync(0xFFFFFFFFu, s, o);
    __shared__ float ws[4], ws2[4];
    int w = t >> 5, l = t & 31;
    if (l == 0) ws[w] = s;
    __syncthreads();
    float mu = (ws[0]+ws[1]+ws[2]+ws[3]) * (1.f/128.f);
    float dv = v - mu;
    float s2 = dv*dv;
    for (int o = 16; o; o >>= 1) s2 += __shfl_xor_sync(0xFFFFFFFFu, s2, o);
    if (l == 0) ws2[w] = s2;
    __syncthreads();
    float var = (ws2[0]+ws2[1]+ws2[2]+ws2[3]) * (1.f/128.f);
    g_q[tok*DQK + t] = dv * rsqrtf(var + 1e-5f) * qln_w[t];
}

// ---------------- fused SVD + two-level top-k ----------------
__global__ __launch_bounds__(256) void select_kernel(const float* __restrict__ core,
                                                     float* __restrict__ d_out, int out_size)
{
    __shared__ float rs[1024];
    __shared__ unsigned long long bufA[16][32];
    __shared__ unsigned long long bufB[8][32];
    __shared__ int ridx[32], cidx[32];
    __shared__ float gg0[32], gg1[32], fc0[32], fc1[32];
    __shared__ float suv[8];   // u0,u1,t0,t1 per head
    int tok = blockIdx.x, tid = threadIdx.x;
    int lane = tid & 31, w = tid >> 5;
    if (tid == 0){
        float aux = 0.f;
        #pragma unroll
        for (int hh = 0; hh < 2; hh++){
            float u0,u1,t0,t1,ap;
            svd2x2(core, hh, u0, u1, t0, t1, ap);
            suv[hh*4+0]=u0; suv[hh*4+1]=u1; suv[hh*4+2]=t0; suv[hh*4+3]=t1;
            aux += ap;
        }
        if (tok == 0 && out_size > OUT_MAIN) d_out[OUT_MAIN] = aux*0.1f;
    }
    #pragma unroll
    for (int e = 0; e < 4; e++) rs[tid + e*256] = g_sc[(size_t)tok*1024 + tid + e*256];
    __syncthreads();
    for (int h = 0; h < 2; h++){
        float u0 = suv[h*4+0], u1 = suv[h*4+1];
        float t0 = suv[h*4+2], t1 = suv[h*4+3];
        float c00 = core[h*4+0], c01 = core[h*4+1], c10 = core[h*4+2], c11 = core[h*4+3];
        {
            int m = w*32 + lane;
            float rv = rs[2*m]*u0 + rs[2*m+1]*u1;
            float cv = rs[512 + 2*m]*t0 + rs[512 + 2*m+1]*t1;
            bufA[w][lane]     = warp_sort_desc(pack_key(rv, (unsigned)m));
            bufA[8 + w][lane] = warp_sort_desc(pack_key(cv, (unsigned)m));
        }
        __syncthreads();
        if (w < 4)
            bufB[w][lane] = warp_merge_desc(bufA[2*w][lane], bufA[2*w+1][lane]);
        else {
            int p = w - 4;
            bufB[4 + p][lane] = warp_merge_desc(bufA[8 + 2*p][lane], bufA[8 + 2*p + 1][lane]);
        }
        __syncthreads();
        if (w < 2)
            bufA[w][lane] = warp_merge_desc(bufB[2*w][lane], bufB[2*w+1][lane]);
        else if (w >= 4 && w < 6){
            int p = w - 4;
            bufA[8 + p][lane] = warp_merge_desc(bufB[4 + 2*p][lane], bufB[4 + 2*p + 1][lane]);
        }
        __syncthreads();
        if (w == 0){
            unsigned long long r = warp_merge_desc(bufA[0][lane], bufA[1][lane]);
            int mi = (int)(0xFFFFFFFFu - (unsigned)r);
            ridx[lane] = mi;
            float f0 = rs[2*mi], f1 = rs[2*mi+1];
            gg0[lane] = f0*c00 + f1*c10;
            gg1[lane] = f0*c01 + f1*c11;
        }
        if (w == 4){
            unsigned long long r = warp_merge_desc(bufA[8][lane], bufA[9][lane]);
            int mi = (int)(0xFFFFFFFFu - (unsigned)r);
            cidx[lane] = mi;
            fc0[lane] = rs[512 + 2*mi];
            fc1[lane] = rs[512 + 2*mi+1];
        }
        __syncthreads();
        unsigned long long v[4];
        #pragma unroll
        for (int c = 0; c < 4; c++){
            int i = w*4 + c;
            float val = gg0[i]*fc0[lane] + gg1[i]*fc1[lane];
            v[c] = warp_sort_desc(pack_key(val, (unsigned)(i*32 + lane)));
        }
        unsigned long long m0 = warp_merge_desc(v[0], v[1]);
        unsigned long long m1 = warp_merge_desc(v[2], v[3]);
        bufA[w][lane] = warp_merge_desc(m0, m1);
        __syncthreads();
        if (w < 4) bufB[w][lane] = warp_merge_desc(bufA[2*w][lane], bufA[2*w+1][lane]);
        __syncthreads();
        if (w < 2) bufA[w][lane] = warp_merge_desc(bufB[2*w][lane], bufB[2*w+1][lane]);
        __syncthreads();
        if (w == 0){
            unsigned long long r = warp_merge_desc(bufA[0][lane], bufA[1][lane]);
            unsigned p = 0xFFFFFFFFu - (unsigned)r;
            float val = unsortable_f((unsigned)(r >> 32));
            g_fs[((size_t)h*TOK + tok)*TOPK + lane] = 1.f/(1.f + expf(-val));
            g_fidx[((size_t)h*TOK + tok)*TOPK + lane] = ridx[p >> 5]*NKEY + cidx[p & 31];
        }
        __syncthreads();
    }
}

__global__ __launch_bounds__(512) void gather_kernel(const float* __restrict__ mem,
                                                     float* __restrict__ out)
{
    int tok = blockIdx.x, tid = threadIdx.x;
    int h = tid >> 8, sub = (tid >> 7) & 1, t = tid & 127;
    __shared__ float w[2][TOPK];
    __shared__ int   id[2][TOPK];
    __shared__ float4 part[2][128];
    if (tid < 64){
        int hh = tid >> 5, k = tid & 31;
        w[hh][k]  = g_fs[((size_t)hh*TOK + tok)*TOPK + k];
        id[hh][k] = g_fidx[((size_t)hh*TOK + tok)*TOPK + k];
    }
    __syncthreads();
    float4 acc = {0.f,0.f,0.f,0.f};
    #pragma unroll
    for (int kk = 0; kk < 16; kk++){
        int k = sub*16 + kk;
        const float4* row = (const float4*)(mem + (size_t)id[h][k]*DV);
        float4 v = __ldg(row + t);
        float ww = w[h][k];
        acc.x += ww*v.x; acc.y += ww*v.y; acc.z += ww*v.z; acc.w += ww*v.w;
    }
    if (sub == 0) part[h][t] = acc;
    __syncthreads();
    if (sub == 1){
        float4 p = part[h][t];
        acc.x += p.x; acc.y += p.y; acc.z += p.z; acc.w += p.w;
        ((float4*)(out + (size_t)tok*1024 + h*DV))[t] = acc;
    }
}

extern "C" void kernel_launch(void* const* d_in, const int* in_sizes, int n_in,
                              void* d_out, int out_size)
{
    const float* tokens  = (const float*)d_in[0];
    const float* rms_w   = (const float*)d_in[1];
    const float* conv_w  = (const float*)d_in[2];
    const float* conv_b  = (const float*)d_in[3];
    const float* wq      = (const float*)d_in[4];
    const float* qln_w   = (const float*)d_in[5];
    const float* keys    = (const float*)d_in[6];
    const float* core    = (const float*)d_in[7];
    const float* mems    = (const float*)d_in[8];
    float* out = (float*)d_out;

    float* qpart; cudaGetSymbolAddress((void**)&qpart, g_qpart);
    float* x2;    cudaGetSymbolAddress((void**)&x2, g_x2);
    float* q;     cudaGetSymbolAddress((void**)&q, g_q);
    float* sc;    cudaGetSymbolAddress((void**)&sc, g_sc);

    rms_kernel<<<TOK, 256>>>(tokens);
    conv_kernel<<<(TOK/4*DIM)/256, 256>>>(tokens, rms_w, conv_w, conv_b);
    gemm_q<<<dim3(2,16,8), 256>>>(x2, wq, qpart);
    ln_kernel<<<TOK, 128>>>(qln_w);
    gemm_sc<<<dim3(16,16,1), 256>>>(q, keys, sc);
    select_kernel<<<TOK, 256>>>(core, out, out_size);
    gather_kernel<<<TOK, 512>>>(mems, out);
}

// round 6
// speedup vs baseline: 2.8396x; 1.2160x over previous
#include <cuda_runtime.h>
#include <cuda_bf16.h>
#include <math.h>

#define BB 2
#define NN 1024
#define TOK (BB*NN)
#define DIM 1024
#define DQK 128
#define NKEY 256
#define TOPK 32
#define DV 512
#define KCONV 5
#define OUT_MAIN (TOK*1024)

__device__ float g_invrms[TOK];
__device__ float g_x2[TOK*DIM];
__device__ float g_qpart[8*TOK*DQK];
__device__ float g_q[TOK*DQK];
__device__ float g_sc[TOK*1024];
__device__ float g_fs[2*TOK*TOPK];
__device__ int   g_fidx[2*TOK*TOPK];

__device__ __forceinline__ float fsign(float a, float b){ return (b >= 0.f) ? fabsf(a) : -fabsf(a); }
__device__ __forceinline__ unsigned sortable_f(float f){
    unsigned u = __float_as_uint(f);
    return (u & 0x80000000u) ? ~u : (u | 0x80000000u);
}
__device__ __forceinline__ float unsortable_f(unsigned s){
    unsigned u = (s & 0x80000000u) ? (s ^ 0x80000000u) : ~s;
    return __uint_as_float(u);
}
__device__ __forceinline__ unsigned long long pack_key(float v, unsigned idx){
    return (((unsigned long long)sortable_f(v)) << 32) | (unsigned long long)(0xFFFFFFFFu - idx);
}

// ---------------- LAPACK slasv2 port ----------------
__device__ void slasv2_dev(float f, float g, float h,
                           float& ssmin, float& ssmax,
                           float& snr, float& csr, float& snl, float& csl)
{
    float ft=f, fa=fabsf(f), ht=h, ha=fabsf(h);
    int pmax = 1;
    bool swp = (ha > fa);
    if (swp){ pmax = 3; float t; t=ft; ft=ht; ht=t; t=fa; fa=ha; ha=t; }
    float gt=g, ga=fabsf(g);
    float clt=0.f, crt=0.f, slt=0.f, srt=0.f;
    if (ga == 0.f){
        ssmin = ha; ssmax = fa; clt=1.f; crt=1.f; slt=0.f; srt=0.f;
    } else {
        bool gasmal = true;
        if (ga > fa){
            pmax = 2;
            if ((fa/ga) < 5.9604645e-08f){
                gasmal = false;
                ssmax = ga;
                ssmin = (ha > 1.f) ? (fa/(ga/ha)) : ((fa/ga)*ha);
                clt = 1.f; slt = ht/gt; srt = 1.f; crt = ft/gt;
            }
        }
        if (gasmal){
            float d_ = fa - ha;
            float l  = (d_ == fa) ? 1.f : d_/fa;
            float m  = gt/ft;
            float t  = 2.f - l;
            float mm = m*m, tt = t*t;
            float s  = sqrtf(tt + mm);
            float r_ = (l == 0.f) ? fabsf(m) : sqrtf(l*l + mm);
            float a_ = 0.5f*(s + r_);
            ssmin = ha/a_;
            ssmax = fa*a_;
            if (mm == 0.f){
                t = (l == 0.f) ? (fsign(2.f, ft)*fsign(1.f, gt))
                               : (gt/fsign(d_, ft) + m/t);
            } else {
                t = (m/(s + t) + m/(r_ + l))*(1.f + a_);
            }
            float l2 = sqrtf(t*t + 4.f);
            crt = 2.f/l2;
            srt = t/l2;
            clt = (crt + srt*m)/a_;
            slt = (ht/ft)*srt/a_;
        }
    }
    if (swp){ csl = srt; snl = crt; csr = slt; snr = clt; }
    else    { csl = clt; snl = slt; csr = crt; snr = srt; }
    float ts = 0.f;
    if (pmax == 1) ts = fsign(1.f, csr)*fsign(1.f, csl)*fsign(1.f, f);
    if (pmax == 2) ts = fsign(1.f, snr)*fsign(1.f, csl)*fsign(1.f, g);
    if (pmax == 3) ts = fsign(1.f, snr)*fsign(1.f, snl)*fsign(1.f, h);
    ssmax = fsign(ssmax, ts);
    ssmin = fsign(ssmin, ts*fsign(1.f, f)*fsign(1.f, h));
}

__device__ void svd2x2(const float* core, int hh, float& u0, float& u1,
                       float& t0, float& t1, float& auxp)
{
    float a = core[hh*4+0], b = core[hh*4+1];
    float c = core[hh*4+2], d = core[hh*4+3];
    float q00=1.f,q01=0.f,q10=0.f,q11=1.f;
    float d1, e1, d2;
    if (c != 0.f){
        float nrm  = sqrtf(a*a + c*c);
        float beta = (a >= 0.f) ? -nrm : nrm;
        float tau  = (beta - a)/beta;
        float v    = c/(a - beta);
        float w    = b + v*d;
        e1 = b - tau*w;
        d2 = d - tau*v*w;
        d1 = beta;
        q00 = 1.f - tau; q01 = -tau*v; q10 = -tau*v; q11 = 1.f - tau*v*v;
    } else { d1 = a; e1 = b; d2 = d; }
    float ssmin, ssmax, snr, csr, snl, csl;
    slasv2_dev(d1, e1, d2, ssmin, ssmax, snr, csr, snl, csl);
    float vt0 = csr, vt1 = snr;
    float s1 = ssmax;
    if (s1 < 0.f){ s1 = -s1; vt0 = -vt0; vt1 = -vt1; }
    float s2 = fabsf(ssmin);
    u0 = q00*csl + q01*snl;
    u1 = q10*csl + q11*snl;
    t0 = vt0;
    t1 = vt1;
    float r = s2 - 0.15f;
    auxp = (r > 0.f) ? r*r : 0.f;
}

__global__ void rms_kernel(const float* __restrict__ tokens)
{
    int tok = blockIdx.x;
    const float4* p = (const float4*)(tokens + (size_t)tok*DIM);
    float4 v = p[threadIdx.x];
    float s = v.x*v.x + v.y*v.y + v.z*v.z + v.w*v.w;
    for (int o = 16; o; o >>= 1) s += __shfl_xor_sync(0xFFFFFFFFu, s, o);
    __shared__ float ws[8];
    if ((threadIdx.x & 31) == 0) ws[threadIdx.x >> 5] = s;
    __syncthreads();
    if (threadIdx.x == 0){
        float t = 0.f;
        #pragma unroll
        for (int i = 0; i < 8; i++) t += ws[i];
        g_invrms[tok] = rsqrtf(t*(1.f/1024.f) + 1.1920929e-07f);
    }
}

__global__ void conv_kernel(const float* __restrict__ tokens,
                            const float* __restrict__ rms_w,
                            const float* __restrict__ conv_w,
                            const float* __restrict__ conv_b)
{
    int gid = blockIdx.x*256 + threadIdx.x;
    int d   = gid & (DIM-1);
    int grp = gid >> 10;
    int ng  = grp & (NN/4 - 1);
    int bb  = grp >> 8;
    float rw = rms_w[d];
    float wv[KCONV];
    #pragma unroll
    for (int k = 0; k < KCONV; k++) wv[k] = conv_w[d*KCONV + k];
    float xv[8];
    #pragma unroll
    for (int j = 0; j < 8; j++){
        int nn = ng*4 - 4 + j;
        if (nn >= 0){
            int t2 = (bb << 10) + nn;
            xv[j] = tokens[(size_t)t2*DIM + d] * g_invrms[t2] * rw;
        } else xv[j] = 0.f;
    }
    float cb = conv_b[d];
    #pragma unroll
    for (int i = 0; i < 4; i++){
        float acc = cb;
        #pragma unroll
        for (int k = 0; k < KCONV; k++) acc += wv[k]*xv[i+k];
        g_x2[(size_t)((bb << 10) + ng*4 + i)*DIM + d] = acc;
    }
}

__global__ __launch_bounds__(256) void gemm_q(const float* __restrict__ A,
                                              const float* __restrict__ B,
                                              float* __restrict__ C)
{
    __shared__ float As[2][16][132];
    __shared__ float Bs[2][16][68];
    int tid = threadIdx.x, tx = tid & 15, ty = tid >> 4;
    int m0 = blockIdx.y*128, n0 = blockIdx.x*64, k0 = blockIdx.z*128;
    C += (size_t)blockIdx.z*(TOK*DQK);
    const float* Ab = A + (size_t)m0*DIM + k0;
    const float* Bb = B + (size_t)n0*DIM + k0;
    float acc[8][4];
    #pragma unroll
    for (int i = 0; i < 8; i++)
        #pragma unroll
        for (int j = 0; j < 4; j++) acc[i][j] = 0.f;
    float ra[8], rb[4];
    #pragma unroll
    for (int e = 0; e < 8; e++){ int f = tid + e*256; ra[e] = Ab[(size_t)(f >> 4)*DIM + (f & 15)]; }
    #pragma unroll
    for (int e = 0; e < 4; e++){ int f = tid + e*256; rb[e] = Bb[(size_t)(f >> 4)*DIM + (f & 15)]; }
    #pragma unroll
    for (int e = 0; e < 8; e++){ int f = tid + e*256; As[0][f & 15][f >> 4] = ra[e]; }
    #pragma unroll
    for (int e = 0; e < 4; e++){ int f = tid + e*256; Bs[0][f & 15][f >> 4] = rb[e]; }
    __syncthreads();
    int cur = 0;
    for (int kk = 0; kk < 128; kk += 16){
        bool nxt = (kk + 16) < 128;
        if (nxt){
            #pragma unroll
            for (int e = 0; e < 8; e++){ int f = tid + e*256; ra[e] = Ab[(size_t)(f >> 4)*DIM + kk + 16 + (f & 15)]; }
            #pragma unroll
            for (int e = 0; e < 4; e++){ int f = tid + e*256; rb[e] = Bb[(size_t)(f >> 4)*DIM + kk + 16 + (f & 15)]; }
        }
        #pragma unroll
        for (int k = 0; k < 16; k++){
            float4 a0 = *(const float4*)&As[cur][k][ty*8];
            float4 a1 = *(const float4*)&As[cur][k][ty*8+4];
            float4 b0 = *(const float4*)&Bs[cur][k][tx*4];
            float a[8] = {a0.x,a0.y,a0.z,a0.w,a1.x,a1.y,a1.z,a1.w};
            float b[4] = {b0.x,b0.y,b0.z,b0.w};
            #pragma unroll
            for (int i = 0; i < 8; i++)
                #pragma unroll
                for (int j = 0; j < 4; j++)
                    acc[i][j] += a[i]*b[j];
        }
        if (nxt){
            #pragma unroll
            for (int e = 0; e < 8; e++){ int f = tid + e*256; As[cur^1][f & 15][f >> 4] = ra[e]; }
            #pragma unroll
            for (int e = 0; e < 4; e++){ int f = tid + e*256; Bs[cur^1][f & 15][f >> 4] = rb[e]; }
            __syncthreads();
            cur ^= 1;
        }
    }
    #pragma unroll
    for (int i = 0; i < 8; i++){
        float4 v = {acc[i][0], acc[i][1], acc[i][2], acc[i][3]};
        *(float4*)(C + (size_t)(m0 + ty*8 + i)*DQK + n0 + tx*4) = v;
    }
}

__global__ __launch_bounds__(256) void gemm_sc(const float* __restrict__ A,
                                               const float* __restrict__ keys,
                                               float* __restrict__ C)
{
    __shared__ float As[2][16][132];
    __shared__ float Bs[2][16][68];
    int tid = threadIdx.x, tx = tid & 15, ty = tid >> 4;
    int m0 = blockIdx.y*128, n0 = blockIdx.x*64;
    const float* Ab = A + (size_t)m0*DQK;
    size_t brow[4];
    #pragma unroll
    for (int e = 0; e < 4; e++){
        int f = tid + e*256;
        int j = n0 + (f >> 4);
        int c = j >> 9, rem = j & 511, m = rem >> 1, r = rem & 1;
        brow[e] = (size_t)(((c*2 + r)*NKEY + m))*DQK;
    }
    float acc[8][4];
    #pragma unroll
    for (int i = 0; i < 8; i++)
        #pragma unroll
        for (int j = 0; j < 4; j++) acc[i][j] = 0.f;
    float ra[8], rb[4];
    #pragma unroll
    for (int e = 0; e < 8; e++){ int f = tid + e*256; ra[e] = Ab[(size_t)(f >> 4)*DQK + (f & 15)]; }
    #pragma unroll
    for (int e = 0; e < 4; e++){ int f = tid + e*256; rb[e] = keys[brow[e] + (f & 15)]; }
    #pragma unroll
    for (int e = 0; e < 8; e++){ int f = tid + e*256; As[0][f & 15][f >> 4] = ra[e]; }
    #pragma unroll
    for (int e = 0; e < 4; e++){ int f = tid + e*256; Bs[0][f & 15][f >> 4] = rb[e]; }
    __syncthreads();
    int cur = 0;
    for (int kk = 0; kk < 128; kk += 16){
        bool nxt = (kk + 16) < 128;
        if (nxt){
            #pragma unroll
            for (int e = 0; e < 8; e++){ int f = tid + e*256; ra[e] = Ab[(size_t)(f >> 4)*DQK + kk + 16 + (f & 15)]; }
            #pragma unroll
            for (int e = 0; e < 4; e++){ int f = tid + e*256; rb[e] = keys[brow[e] + kk + 16 + (f & 15)]; }
        }
        #pragma unroll
        for (int k = 0; k < 16; k++){
            float4 a0 = *(const float4*)&As[cur][k][ty*8];
            float4 a1 = *(const float4*)&As[cur][k][ty*8+4];
            float4 b0 = *(const float4*)&Bs[cur][k][tx*4];
            float a[8] = {a0.x,a0.y,a0.z,a0.w,a1.x,a1.y,a1.z,a1.w};
            float b[4] = {b0.x,b0.y,b0.z,b0.w};
            #pragma unroll
            for (int i = 0; i < 8; i++)
                #pragma unroll
                for (int j = 0; j < 4; j++)
                    acc[i][j] += a[i]*b[j];
        }
        if (nxt){
            #pragma unroll
            for (int e = 0; e < 8; e++){ int f = tid + e*256; As[cur^1][f & 15][f >> 4] = ra[e]; }
            #pragma unroll
            for (int e = 0; e < 4; e++){ int f = tid + e*256; Bs[cur^1][f & 15][f >> 4] = rb[e]; }
            __syncthreads();
            cur ^= 1;
        }
    }
    #pragma unroll
    for (int i = 0; i < 8; i++){
        float4 v = {acc[i][0], acc[i][1], acc[i][2], acc[i][3]};
        *(float4*)(C + (size_t)(m0 + ty*8 + i)*1024 + n0 + tx*4) = v;
    }
}

__global__ void ln_kernel(const float* __restrict__ qln_w)
{
    int tok = blockIdx.x, t = threadIdx.x;
    float v = 0.f;
    #pragma unroll
    for (int z = 0; z < 8; z++) v += g_qpart[(size_t)z*TOK*DQK + tok*DQK + t];
    float s = v;
    for (int o = 16; o; o >>= 1) s += __shfl_xor_sync(0xFFFFFFFFu, s, o);
    __shared__ float ws[4], ws2[4];
    int w = t >> 5, l = t & 31;
    if (l == 0) ws[w] = s;
    __syncthreads();
    float mu = (ws[0]+ws[1]+ws[2]+ws[3]) * (1.f/128.f);
    float dv = v - mu;
    float s2 = dv*dv;
    for (int o = 16; o; o >>= 1) s2 += __shfl_xor_sync(0xFFFFFFFFu, s2, o);
    if (l == 0) ws2[w] = s2;
    __syncthreads();
    float var = (ws2[0]+ws2[1]+ws2[2]+ws2[3]) * (1.f/128.f);
    g_q[tok*DQK + t] = dv * rsqrtf(var + 1e-5f) * qln_w[t];
}

// ---------------- block-wide exact top-32 threshold via MSB radix descent ----------------
// Returns threshold T such that { key : key >= T } has exactly 32 members.
// Keys must be unique (guaranteed: index embedded in low bits).
__device__ unsigned long long radix_select32(const unsigned long long* kv, int npt, int tid,
                                             unsigned* hist, unsigned* sh)
{
    // sh[0]=D, sh[1]=need', sh[2]=done, sh[8..15]=per-warp suffix sums
    unsigned long long prefix = 0;
    bool act[4] = {true, true, true, true};
    int need = 32;
    int lane = tid & 31, w = tid >> 5;
    for (int shift = 56; shift >= 0; shift -= 8){
        hist[tid] = 0;
        __syncthreads();
        #pragma unroll
        for (int e = 0; e < 4; e++)
            if (e < npt && act[e])
                atomicAdd(&hist[(unsigned)((kv[e] >> shift) & 255)], 1u);
        __syncthreads();
        unsigned h = hist[tid];
        unsigned inc = h;
        #pragma unroll
        for (int off = 1; off < 32; off <<= 1){
            unsigned v = __shfl_down_sync(0xFFFFFFFFu, inc, off);
            if (lane + off < 32) inc += v;
        }
        if (lane == 0) sh[8 + w] = inc;
        __syncthreads();
        unsigned upper = 0;
        #pragma unroll
        for (int ww = 1; ww < 8; ww++) if (ww > w) upper += sh[8 + ww];
        unsigned cge = inc + upper;        // # active keys with digit >= tid
        unsigned cgt = cge - h;            // # active keys with digit >  tid
        if (cgt < (unsigned)need && cge >= (unsigned)need){
            sh[0] = (unsigned)tid;
            sh[1] = (unsigned)need - cgt;
            sh[2] = (h == (unsigned)need - cgt) ? 1u : 0u;
        }
        __syncthreads();
        unsigned D = sh[0];
        need = (int)sh[1];
        unsigned done = sh[2];
        prefix |= ((unsigned long long)D) << shift;
        if (done) return prefix;           // all keys >= prefix are selected, exactly 32
        #pragma unroll
        for (int e = 0; e < 4; e++)
            if (e < npt)
                act[e] = act[e] && (((kv[e] >> shift) & 255) == (unsigned long long)D);
        __syncthreads();
    }
    return prefix;   // unreachable for unique keys (resolves by shift=0)
}

// ---------------- fused SVD + two-level top-k (radix select, no sorting) ----------------
__global__ __launch_bounds__(256) void select_kernel(const float* __restrict__ core,
                                                     float* __restrict__ d_out, int out_size)
{
    __shared__ float rs[1024];
    __shared__ unsigned hist[256];
    __shared__ unsigned sh[16];
    __shared__ int ridx[32], cidx[32];
    __shared__ float gg0[32], gg1[32], fc0[32], fc1[32];
    __shared__ float suv[8];
    __shared__ int cnt;
    int tok = blockIdx.x, tid = threadIdx.x;
    if (tid == 0){
        float aux = 0.f;
        #pragma unroll
        for (int hh = 0; hh < 2; hh++){
            float u0,u1,t0,t1,ap;
            svd2x2(core, hh, u0, u1, t0, t1, ap);
            suv[hh*4+0]=u0; suv[hh*4+1]=u1; suv[hh*4+2]=t0; suv[hh*4+3]=t1;
            aux += ap;
        }
        if (tok == 0 && out_size > OUT_MAIN) d_out[OUT_MAIN] = aux*0.1f;
    }
    #pragma unroll
    for (int e = 0; e < 4; e++) rs[tid + e*256] = g_sc[(size_t)tok*1024 + tid + e*256];
    __syncthreads();

    for (int h = 0; h < 2; h++){
        float u0 = suv[h*4+0], u1 = suv[h*4+1];
        float t0 = suv[h*4+2], t1 = suv[h*4+3];
        float c00 = core[h*4+0], c01 = core[h*4+1], c10 = core[h*4+2], c11 = core[h*4+3];

        // ---- row top-32 of 256 ----
        if (tid == 0) cnt = 0;
        unsigned long long kr = pack_key(rs[2*tid]*u0 + rs[2*tid+1]*u1, (unsigned)tid);
        unsigned long long T = radix_select32(&kr, 1, tid, hist, sh);
        if (kr >= T){ int s = atomicAdd(&cnt, 1); ridx[s] = tid; }
        __syncthreads();
        if (tid < 32){
            int mi = ridx[tid];
            float f0 = rs[2*mi], f1 = rs[2*mi+1];
            gg0[tid] = f0*c00 + f1*c10;
            gg1[tid] = f0*c01 + f1*c11;
        }

        // ---- col top-32 of 256 ----
        if (tid == 0) cnt = 0;
        unsigned long long kc = pack_key(rs[512 + 2*tid]*t0 + rs[512 + 2*tid+1]*t1, (unsigned)tid);
        T = radix_select32(&kc, 1, tid, hist, sh);
        if (kc >= T){ int s = atomicAdd(&cnt, 1); cidx[s] = tid; }
        __syncthreads();
        if (tid < 32){
            int mi = cidx[tid];
            fc0[tid] = rs[512 + 2*mi];
            fc1[tid] = rs[512 + 2*mi+1];
        }
        __syncthreads();

        // ---- stage B: top-32 of the 32x32 score grid ----
        if (tid == 0) cnt = 0;
        unsigned long long kv[4];
        #pragma unroll
        for (int c = 0; c < 4; c++){
            int p = c*256 + tid;
            int i = p >> 5, j = p & 31;
            float val = gg0[i]*fc0[j] + gg1[i]*fc1[j];
            kv[c] = pack_key(val, (unsigned)p);
        }
        T = radix_select32(kv, 4, tid, hist, sh);
        #pragma unroll
        for (int c = 0; c < 4; c++){
            if (kv[c] >= T){
                int s = atomicAdd(&cnt, 1);
                int p = (int)(0xFFFFFFFFu - (unsigned)(kv[c] & 0xFFFFFFFFu));
                float val = unsortable_f((unsigned)(kv[c] >> 32));
                g_fs[((size_t)h*TOK + tok)*TOPK + s] = 1.f/(1.f + expf(-val));
                g_fidx[((size_t)h*TOK + tok)*TOPK + s] = ridx[p >> 5]*NKEY + cidx[p & 31];
            }
        }
        __syncthreads();
    }
}

__global__ __launch_bounds__(512) void gather_kernel(const float* __restrict__ mem,
                                                     float* __restrict__ out)
{
    int tok = blockIdx.x, tid = threadIdx.x;
    int h = tid >> 8, sub = (tid >> 7) & 1, t = tid & 127;
    __shared__ float w[2][TOPK];
    __shared__ int   id[2][TOPK];
    __shared__ float4 part[2][128];
    if (tid < 64){
        int hh = tid >> 5, k = tid & 31;
        w[hh][k]  = g_fs[((size_t)hh*TOK + tok)*TOPK + k];
        id[hh][k] = g_fidx[((size_t)hh*TOK + tok)*TOPK + k];
    }
    __syncthreads();
    float4 acc = {0.f,0.f,0.f,0.f};
    #pragma unroll
    for (int kk = 0; kk < 16; kk++){
        int k = sub*16 + kk;
        const float4* row = (const float4*)(mem + (size_t)id[h][k]*DV);
        float4 v = __ldg(row + t);
        float ww = w[h][k];
        acc.x += ww*v.x; acc.y += ww*v.y; acc.z += ww*v.z; acc.w += ww*v.w;
    }
    if (sub == 0) part[h][t] = acc;
    __syncthreads();
    if (sub == 1){
        float4 p = part[h][t];
        acc.x += p.x; acc.y += p.y; acc.z += p.z; acc.w += p.w;
        ((float4*)(out + (size_t)tok*1024 + h*DV))[t] = acc;
    }
}

extern "C" void kernel_launch(void* const* d_in, const int* in_sizes, int n_in,
                              void* d_out, int out_size)
{
    const float* tokens  = (const float*)d_in[0];
    const float* rms_w   = (const float*)d_in[1];
    const float* conv_w  = (const float*)d_in[2];
    const float* conv_b  = (const float*)d_in[3];
    const float* wq      = (const float*)d_in[4];
    const float* qln_w   = (const float*)d_in[5];
    const float* keys    = (const float*)d_in[6];
    const float* core    = (const float*)d_in[7];
    const float* mems    = (const float*)d_in[8];
    float* out = (float*)d_out;

    float* qpart; cudaGetSymbolAddress((void**)&qpart, g_qpart);
    float* x2;    cudaGetSymbolAddress((void**)&x2, g_x2);
    float* q;     cudaGetSymbolAddress((void**)&q, g_q);
    float* sc;    cudaGetSymbolAddress((void**)&sc, g_sc);

    rms_kernel<<<TOK, 256>>>(tokens);
    conv_kernel<<<(TOK/4*DIM)/256, 256>>>(tokens, rms_w, conv_w, conv_b);
    gemm_q<<<dim3(2,16,8), 256>>>(x2, wq, qpart);
    ln_kernel<<<TOK, 128>>>(qln_w);
    gemm_sc<<<dim3(16,16,1), 256>>>(q, keys, sc);
    select_kernel<<<TOK, 256>>>(core, out, out_size);
    gather_kernel<<<TOK, 512>>>(mems, out);
}